// round 11
// baseline (speedup 1.0000x reference)
#include <cuda_runtime.h>
#include <cuda_fp16.h>
#include <cstdint>

// out(4096,128) = input(4096,49998) @ word2vecs[0:49998](49998,128), fp32.
// fp16 m16n8k16 mma.sync path (same 11-bit significand as tf32 -> same error;
// tcgen05 unavailable: harness PTX target is compute_103, no 'a' features).
#define KDIM 49998
#define MDIM 4096
#define NDIM 128
#define KPAD 50048             // BT row stride in halves (zero-padded)
#define SPLITS 9
#define KSPLIT 5568            // 87*64 ; 9*5568 >= KDIM
#define BM 128
#define BK 64
#define STAGES 3
#define NTHREADS 512
#define RSA32 68               // A fp32 smem row stride (floats): 64 + 4 pad
#define RSH 72                 // fp16 smem row stride (halves): 144B, 16B-multiple
#define A32_BYTES (BM * RSA32 * 4)          // 34816
#define B16_BYTES (BM * RSH * 2)            // 18432
#define A16_BYTES (BM * RSH * 2)            // 18432
#define SMEM_A32(s) ((s) * A32_BYTES)                                   // 0 .. 104448
#define SMEM_B16(s) (3 * A32_BYTES + (s) * B16_BYTES)                   // 104448 ..
#define SMEM_A16(d) (3 * A32_BYTES + 3 * B16_BYTES + (d) * A16_BYTES)   // 159744 ..
#define SMEM_TOTAL  (SMEM_A16(2))                                       // 196608 -> 1 CTA/SM

__device__ __half g_bt16[(size_t)NDIM * KPAD];           // B^T fp16, zero-padded
__device__ float  g_part[(size_t)SPLITS * MDIM * NDIM];  // split-K partials
__device__ int    g_cnt[MDIM / BM];                      // per-tile arrival counters

// ---------------- helpers ----------------
__device__ __forceinline__ uint32_t smem_u32(const void* p) {
    uint32_t a;
    asm("{ .reg .u64 t; cvta.to.shared.u64 t, %1; cvt.u32.u64 %0, t; }" : "=r"(a) : "l"(p));
    return a;
}
__device__ __forceinline__ void cp8(uint32_t dst, const void* src) {
    asm volatile("cp.async.ca.shared.global [%0], [%1], 8;" :: "r"(dst), "l"(src));
}
__device__ __forceinline__ void cp8p(uint32_t dst, const void* src, uint32_t nbytes) {
    asm volatile("cp.async.ca.shared.global [%0], [%1], 8, %2;" :: "r"(dst), "l"(src), "r"(nbytes));
}
__device__ __forceinline__ void cp16(uint32_t dst, const void* src) {
    asm volatile("cp.async.cg.shared.global [%0], [%1], 16;" :: "r"(dst), "l"(src));
}
__device__ __forceinline__ void cp16p(uint32_t dst, const void* src, uint32_t nbytes) {
    asm volatile("cp.async.cg.shared.global [%0], [%1], 16, %2;" :: "r"(dst), "l"(src), "r"(nbytes));
}
__device__ __forceinline__ void cp_commit() { asm volatile("cp.async.commit_group;" ::: "memory"); }
__device__ __forceinline__ void cp_wait1() { asm volatile("cp.async.wait_group 1;" ::: "memory"); }
__device__ __forceinline__ void cp_wait0() { asm volatile("cp.async.wait_group 0;" ::: "memory"); }

__device__ __forceinline__ uint32_t pack_h2(float hi, float lo) {
    uint32_t d;
    asm("cvt.rn.f16x2.f32 %0, %1, %2;" : "=r"(d) : "f"(hi), "f"(lo));
    return d;
}
__device__ __forceinline__ void ldsm4(uint32_t& r0, uint32_t& r1, uint32_t& r2, uint32_t& r3,
                                      uint32_t addr) {
    asm volatile("ldmatrix.sync.aligned.m8n8.x4.shared.b16 {%0,%1,%2,%3}, [%4];"
                 : "=r"(r0), "=r"(r1), "=r"(r2), "=r"(r3) : "r"(addr));
}
__device__ __forceinline__ void mma_fp16(float* c, const uint32_t* a, uint32_t b0, uint32_t b1) {
    asm volatile(
        "mma.sync.aligned.m16n8k16.row.col.f32.f16.f16.f32 "
        "{%0,%1,%2,%3}, {%4,%5,%6,%7}, {%8,%9}, {%0,%1,%2,%3};"
        : "+f"(c[0]), "+f"(c[1]), "+f"(c[2]), "+f"(c[3])
        : "r"(a[0]), "r"(a[1]), "r"(a[2]), "r"(a[3]), "r"(b0), "r"(b1));
}

// ------- kernel 1: transpose + fp16-convert B -> g_bt16[n][k] zero-padded; reset counters -------
__global__ void prep_b(const float* __restrict__ w2v) {
    __shared__ float tile[32][33];
    int k0 = blockIdx.x * 32;
    int n0 = blockIdx.y * 32;
    int tx = threadIdx.x, ty = threadIdx.y;  // 32 x 8
#pragma unroll
    for (int i = 0; i < 32; i += 8) {
        int k = k0 + ty + i;
        float v = 0.f;
        if (k < KDIM) v = w2v[(size_t)k * NDIM + n0 + tx];
        tile[ty + i][tx] = v;
    }
    __syncthreads();
#pragma unroll
    for (int i = 0; i < 32; i += 8) {
        int n = n0 + ty + i;
        g_bt16[(size_t)n * KPAD + k0 + tx] = __float2half_rn(tile[tx][ty + i]);
    }
    if (blockIdx.x == 0 && blockIdx.y == 0) {
        int tid = ty * 32 + tx;
        if (tid < MDIM / BM) g_cnt[tid] = 0;
    }
}

// ------- kernel 2: fp16 mma.sync GEMM, BK=64, convert-ahead (1 barrier/iter), split-K -------
__global__ void __launch_bounds__(NTHREADS, 1) gemm_fp16(float* __restrict__ out,
                                                         const float* __restrict__ A) {
    extern __shared__ char smem[];
    const uint32_t sb = smem_u32(smem);
    const int tid = threadIdx.x;
    const int wid = tid >> 5, lane = tid & 31;
    const int lr = lane >> 2, lk = lane & 3;

    const int tile = blockIdx.x;
    const int m0 = tile * BM;
    const int split = blockIdx.y;
    const int klo = split * KSPLIT;
    const int khi = min(KDIM, klo + KSPLIT);
    const int iters = (khi - klo + BK - 1) / BK;   // 87 (86 for last split)

    const int wm = (wid & 3) * 32;   // warp M offset (4 x 32 rows)
    const int wc = (wid >> 2) * 32;  // warp N offset (4 x 32 cols)

    const uint32_t lm_off = ((uint32_t)(lane & 15) * RSH + (uint32_t)((lane >> 4) << 3)) * 2u;

    // ---- per-thread load slots (this thread converts exactly what it loads) ----
    const float* a_base = A + (size_t)m0 * KDIM + klo;
    const __half* b_base = g_bt16 + klo;
    // even-row cp16 slots (j=0,1): row re+64j, floats [4ge, 4ge+4)
    const int re = 2 * (tid >> 4), ge = tid & 15;
    const uint32_t aoff_e = (uint32_t)re * KDIM + (uint32_t)ge * 4;     // + j*64*KDIM
    const uint32_t d32_e = (uint32_t)(re * RSA32 + ge * 4) * 4u;        // + j*64*RSA32*4
    const uint32_t d16_e = (uint32_t)(re * RSH + ge * 4) * 2u;          // + j*64*RSH*2
    // odd-row cp8 slots (j=0..3): row ro+32j, floats [2go, 2go+2)
    const int ro = 2 * (tid >> 5) + 1, go = tid & 31;
    const uint32_t aoff_o = (uint32_t)ro * KDIM + (uint32_t)go * 2;     // + j*32*KDIM
    const uint32_t d32_o = (uint32_t)(ro * RSA32 + go * 2) * 4u;        // + j*32*RSA32*4
    const uint32_t d16_o = (uint32_t)(ro * RSH + go * 2) * 2u;          // + j*32*RSH*2
    // B cp16 slots (j=0,1): n-row nb, halves [8*(gb+4j), +8)
    const int nb = tid >> 2, gb = tid & 3;
    const uint32_t boff = (uint32_t)nb * KPAD + (uint32_t)gb * 8;       // + j*32 halves
    const uint32_t d_b = (uint32_t)(nb * RSH + gb * 8) * 2u;            // + j*64 bytes

    float acc[2][4][4];
#pragma unroll
    for (int mi = 0; mi < 2; mi++)
#pragma unroll
        for (int ni = 0; ni < 4; ni++)
#pragma unroll
            for (int q = 0; q < 4; q++) acc[mi][ni][q] = 0.f;

    auto load_stage = [&](int stage) {
        const uint32_t a32 = sb + SMEM_A32(stage % STAGES);
        const uint32_t b16 = sb + SMEM_B16(stage % STAGES);
        const int koff = stage * BK;
        const int k0 = klo + koff;
        if (k0 + BK <= khi) {
#pragma unroll
            for (int j = 0; j < 2; j++)
                cp16(a32 + d32_e + (uint32_t)(j * 64 * RSA32 * 4),
                     a_base + aoff_e + (uint32_t)j * 64u * KDIM + koff);
#pragma unroll
            for (int j = 0; j < 4; j++)
                cp8(a32 + d32_o + (uint32_t)(j * 32 * RSA32 * 4),
                    a_base + aoff_o + (uint32_t)j * 32u * KDIM + koff);
#pragma unroll
            for (int j = 0; j < 2; j++)
                cp16(b16 + d_b + (uint32_t)(j * 64),
                     b_base + boff + (uint32_t)(j * 32) + koff);
        } else {
            // tail (last iter of last split only)
#pragma unroll
            for (int j = 0; j < 2; j++) {
                int kk = k0 + ge * 4;
                uint32_t n = (uint32_t)min(16, max(0, (khi - kk) * 4));
                const float* s = a_base + aoff_e + (uint32_t)j * 64u * KDIM + koff;
                cp16p(a32 + d32_e + (uint32_t)(j * 64 * RSA32 * 4), n ? (const void*)s : (const void*)A, n);
            }
#pragma unroll
            for (int j = 0; j < 4; j++) {
                int kk = k0 + go * 2;
                uint32_t n = (uint32_t)min(8, max(0, (khi - kk) * 4));
                const float* s = a_base + aoff_o + (uint32_t)j * 32u * KDIM + koff;
                cp8p(a32 + d32_o + (uint32_t)(j * 32 * RSA32 * 4), n ? (const void*)s : (const void*)A, n);
            }
#pragma unroll
            for (int j = 0; j < 2; j++)   // B padded/zero-filled -> always safe
                cp16(b16 + d_b + (uint32_t)(j * 64),
                     b_base + boff + (uint32_t)(j * 32) + koff);
        }
        cp_commit();
    };

    // convert stage s (A32[s%3]) -> A16[s&1]; each thread converts ONLY its own granules
    auto convert_stage = [&](int stage) {
        const char* a32 = smem + SMEM_A32(stage % STAGES);
        char* a16 = smem + SMEM_A16(stage & 1);
#pragma unroll
        for (int j = 0; j < 2; j++) {
            float4 v = *reinterpret_cast<const float4*>(a32 + d32_e + (uint32_t)(j * 64 * RSA32 * 4));
            uint2 p = make_uint2(pack_h2(v.y, v.x), pack_h2(v.w, v.z));
            *reinterpret_cast<uint2*>(a16 + d16_e + (uint32_t)(j * 64 * RSH * 2)) = p;
        }
#pragma unroll
        for (int j = 0; j < 4; j++) {
            float2 v = *reinterpret_cast<const float2*>(a32 + d32_o + (uint32_t)(j * 32 * RSA32 * 4));
            *reinterpret_cast<uint32_t*>(a16 + d16_o + (uint32_t)(j * 32 * RSH * 2)) = pack_h2(v.y, v.x);
        }
    };

    // prologue: stages 0,1 in flight; convert stage 0 (own data; group 0 done after wait1)
    load_stage(0);
    load_stage(1);
    cp_wait1();
    convert_stage(0);

    for (int i = 0; i < iters; i++) {
        __syncthreads();   // the ONLY barrier per iter: A16[i&1] visible, WAR on reloaded bufs
        if (i + 2 < iters) load_stage(i + 2);

        // MMAs on stage i: A16[i&1] (converted last iter), B16[i%3] (arrived; waited last iter)
        const uint32_t a16 = sb + SMEM_A16(i & 1) + lm_off + (uint32_t)(wm * RSH * 2);
        const uint32_t b16 = sb + SMEM_B16(i % STAGES) + lm_off + (uint32_t)(wc * RSH * 2);
#pragma unroll
        for (int ks = 0; ks < 4; ks++) {
            uint32_t a[2][4], bf[2][4];
#pragma unroll
            for (int mi = 0; mi < 2; mi++)
                ldsm4(a[mi][0], a[mi][1], a[mi][2], a[mi][3],
                      a16 + (uint32_t)(mi * 16 * RSH * 2) + (uint32_t)(ks * 32));
#pragma unroll
            for (int nj = 0; nj < 2; nj++)
                ldsm4(bf[nj][0], bf[nj][1], bf[nj][2], bf[nj][3],
                      b16 + (uint32_t)(nj * 16 * RSH * 2) + (uint32_t)(ks * 32));
#pragma unroll
            for (int mi = 0; mi < 2; mi++) {
                mma_fp16(acc[mi][0], a[mi], bf[0][0], bf[0][2]);
                mma_fp16(acc[mi][1], a[mi], bf[0][1], bf[0][3]);
                mma_fp16(acc[mi][2], a[mi], bf[1][0], bf[1][2]);
                mma_fp16(acc[mi][3], a[mi], bf[1][1], bf[1][3]);
            }
        }

        // convert-ahead: stage i+1 -> A16[(i+1)&1], off the MMA critical path
        if (i + 1 < iters) {
            if (i + 2 < iters) cp_wait1(); else cp_wait0();
            convert_stage(i + 1);
        }
    }

    // write this split's partial
    float* base = g_part + (size_t)split * MDIM * NDIM;
#pragma unroll
    for (int mi = 0; mi < 2; mi++) {
        int r0 = m0 + wm + mi * 16 + lr;
#pragma unroll
        for (int ni = 0; ni < 4; ni++) {
            int c0 = wc + ni * 8 + 2 * lk;
            *reinterpret_cast<float2*>(base + (size_t)r0 * NDIM + c0) =
                make_float2(acc[mi][ni][0], acc[mi][ni][1]);
            *reinterpret_cast<float2*>(base + (size_t)(r0 + 8) * NDIM + c0) =
                make_float2(acc[mi][ni][2], acc[mi][ni][3]);
        }
    }

    // fused reduction: last CTA for this tile sums all splits in fixed order (deterministic)
    __threadfence();
    __shared__ int s_last;
    __syncthreads();
    if (tid == 0) s_last = (atomicAdd(&g_cnt[tile], 1) == SPLITS - 1) ? 1 : 0;
    __syncthreads();
    if (s_last) {
        const size_t t4 = (size_t)m0 * NDIM / 4;
#pragma unroll
        for (int j = 0; j < 8; j++) {
            size_t idx = t4 + (size_t)tid + (size_t)j * NTHREADS;
            float4 a4 = __ldcg(reinterpret_cast<const float4*>(g_part) + idx);
#pragma unroll
            for (int s = 1; s < SPLITS; s++) {
                float4 v = __ldcg(reinterpret_cast<const float4*>(g_part) +
                                  (size_t)s * (MDIM * NDIM / 4) + idx);
                a4.x += v.x; a4.y += v.y; a4.z += v.z; a4.w += v.w;
            }
            reinterpret_cast<float4*>(out)[idx] = a4;
        }
    }
}

// ---------------- launch ----------------
extern "C" void kernel_launch(void* const* d_in, const int* in_sizes, int n_in,
                              void* d_out, int out_size) {
    const float* input = (const float*)d_in[0];
    const float* w2v   = (const float*)d_in[1];
    if (n_in >= 2 && in_sizes[0] == 50000 * 128) {  // defensive: identify by size
        input = (const float*)d_in[1];
        w2v   = (const float*)d_in[0];
    }
    cudaFuncSetAttribute(gemm_fp16, cudaFuncAttributeMaxDynamicSharedMemorySize, SMEM_TOTAL);

    prep_b<<<dim3(KPAD / 32, NDIM / 32), dim3(32, 8)>>>(w2v);
    gemm_fp16<<<dim3(MDIM / BM, SPLITS), NTHREADS, SMEM_TOTAL>>>((float*)d_out, input);
}

// round 12
// speedup vs baseline: 1.3207x; 1.3207x over previous
#include <cuda_runtime.h>
#include <cuda_fp16.h>
#include <cstdint>

// out(4096,128) = input(4096,49998) @ word2vecs[0:49998](49998,128), fp32.
// fp16 m16n8k16 mma.sync path (same 11-bit significand as tf32 -> same error;
// tcgen05 unavailable: harness PTX target is compute_103, no 'a' features).
#define KDIM 49998
#define MDIM 4096
#define NDIM 128
#define KPAD 50048             // BT row stride in halves (zero-padded)
#define SPLITS 9
#define KSPLIT 5568            // 174*32 ; 9*5568 >= KDIM
#define BM 128
#define BK 32
#define STAGES 3
#define NTHREADS 256
#define RSH 40                 // fp16 smem row stride (halves); 80B = 16B-mult
#define B16_BYTES (BM * RSH * 2)            // 10240
#define A16_BYTES (BM * RSH * 2)            // 10240
#define SMEM_B16(s) ((s) * B16_BYTES)                    // 0 .. 30720
#define SMEM_A16(d) (3 * B16_BYTES + (d) * A16_BYTES)    // 30720 ..
#define SMEM_TOTAL  (SMEM_A16(2))                        // 51200 -> 2 CTAs/SM (reg-capped)

__device__ __half g_bt16[(size_t)NDIM * KPAD];           // B^T fp16, zero-padded
__device__ float  g_part[(size_t)SPLITS * MDIM * NDIM];  // split-K partials
__device__ int    g_cnt[MDIM / BM];                      // per-tile arrival counters

// ---------------- helpers ----------------
__device__ __forceinline__ uint32_t smem_u32(const void* p) {
    uint32_t a;
    asm("{ .reg .u64 t; cvta.to.shared.u64 t, %1; cvt.u32.u64 %0, t; }" : "=r"(a) : "l"(p));
    return a;
}
__device__ __forceinline__ void cp16(uint32_t dst, const void* src) {
    asm volatile("cp.async.cg.shared.global [%0], [%1], 16;" :: "r"(dst), "l"(src));
}
__device__ __forceinline__ void cp_commit() { asm volatile("cp.async.commit_group;" ::: "memory"); }
__device__ __forceinline__ void cp_wait1() { asm volatile("cp.async.wait_group 1;" ::: "memory"); }
__device__ __forceinline__ void cp_wait0() { asm volatile("cp.async.wait_group 0;" ::: "memory"); }

__device__ __forceinline__ uint32_t pack_h2(float hi, float lo) {
    uint32_t d;
    asm("cvt.rn.f16x2.f32 %0, %1, %2;" : "=r"(d) : "f"(hi), "f"(lo));
    return d;
}
__device__ __forceinline__ void ldsm4(uint32_t& r0, uint32_t& r1, uint32_t& r2, uint32_t& r3,
                                      uint32_t addr) {
    asm volatile("ldmatrix.sync.aligned.m8n8.x4.shared.b16 {%0,%1,%2,%3}, [%4];"
                 : "=r"(r0), "=r"(r1), "=r"(r2), "=r"(r3) : "r"(addr));
}
__device__ __forceinline__ void mma_fp16(float* c, const uint32_t* a, uint32_t b0, uint32_t b1) {
    asm volatile(
        "mma.sync.aligned.m16n8k16.row.col.f32.f16.f16.f32 "
        "{%0,%1,%2,%3}, {%4,%5,%6,%7}, {%8,%9}, {%0,%1,%2,%3};"
        : "+f"(c[0]), "+f"(c[1]), "+f"(c[2]), "+f"(c[3])
        : "r"(a[0]), "r"(a[1]), "r"(a[2]), "r"(a[3]), "r"(b0), "r"(b1));
}

// ------- kernel 1: transpose + fp16-convert B -> g_bt16[n][k] zero-padded; reset counters -------
__global__ void prep_b(const float* __restrict__ w2v) {
    __shared__ float tile[32][33];
    int k0 = blockIdx.x * 32;
    int n0 = blockIdx.y * 32;
    int tx = threadIdx.x, ty = threadIdx.y;  // 32 x 8
#pragma unroll
    for (int i = 0; i < 32; i += 8) {
        int k = k0 + ty + i;
        float v = 0.f;
        if (k < KDIM) v = w2v[(size_t)k * NDIM + n0 + tx];
        tile[ty + i][tx] = v;
    }
    __syncthreads();
#pragma unroll
    for (int i = 0; i < 32; i += 8) {
        int n = n0 + ty + i;
        g_bt16[(size_t)n * KPAD + k0 + tx] = __float2half_rn(tile[tx][ty + i]);
    }
    if (blockIdx.x == 0 && blockIdx.y == 0) {
        int tid = ty * 32 + tx;
        if (tid < MDIM / BM) g_cnt[tid] = 0;
    }
}

// ------- kernel 2: fp16 mma.sync GEMM; A via LDG->reg->cvt->STS; 1 barrier/iter; split-K -------
__global__ void __launch_bounds__(NTHREADS, 2) gemm_fp16(float* __restrict__ out,
                                                         const float* __restrict__ A) {
    extern __shared__ char smem[];
    const uint32_t sb = smem_u32(smem);
    const int tid = threadIdx.x;
    const int wid = tid >> 5, lane = tid & 31;
    const int lr = lane >> 2, lk = lane & 3;

    const int tile = blockIdx.x;
    const int m0 = tile * BM;
    const int split = blockIdx.y;
    const int klo = split * KSPLIT;
    const int khi = min(KDIM, klo + KSPLIT);
    const int iters = (khi - klo + BK - 1) / BK;

    const int wm = (wid & 1) * 64;   // warp M offset
    const int wc = (wid >> 1) * 32;  // warp N offset

    const uint32_t lm_off = ((uint32_t)(lane & 15) * RSH + (uint32_t)((lane >> 4) << 3)) * 2u;

    // ---- per-thread A slots (LDG direct; same thread converts what it loads) ----
    const float* a_base = A + (size_t)m0 * KDIM + klo;
    // even-row float4 slots (j=0,1): row re+64j, floats [4ge, 4ge+4)  (16B-aligned)
    const int re = 2 * (tid >> 3), ge = tid & 7;
    const uint32_t aoff_e = (uint32_t)re * KDIM + (uint32_t)ge * 4;     // + j*64*KDIM
    const uint32_t d16_e = (uint32_t)(re * RSH + ge * 4) * 2u;          // + j*64*RSH*2
    // odd-row float2 slots (j=0..3): row ro+32j, floats [2go, 2go+2)  (8B-aligned)
    const int ro = 2 * (tid >> 4) + 1, go = tid & 15;
    const uint32_t aoff_o = (uint32_t)ro * KDIM + (uint32_t)go * 2;     // + j*32*KDIM
    const uint32_t d16_o = (uint32_t)(ro * RSH + go * 2) * 2u;          // + j*32*RSH*2
    // B cp16 slots (j=0,1): n-row nb+64j, halves [8gb, 8gb+8)
    const int nb = tid >> 2, gb = tid & 3;
    const uint32_t boff = (uint32_t)nb * KPAD + (uint32_t)gb * 8;       // + j*64*KPAD
    const uint32_t d_b = (uint32_t)(nb * RSH + gb * 8) * 2u;            // + j*64*RSH*2
    const __half* b_base = g_bt16 + klo;

    float4 ebuf[2];                  // A register stage (even rows)
    float2 obuf[4];                  // A register stage (odd rows)

    float acc[4][4][4];
#pragma unroll
    for (int mi = 0; mi < 4; mi++)
#pragma unroll
        for (int ni = 0; ni < 4; ni++)
#pragma unroll
            for (int q = 0; q < 4; q++) acc[mi][ni][q] = 0.f;

    // LDG stage -> register buffer (guarded only on the tail stage)
    auto ldg_stage = [&](int stage) {
        const int koff = stage * BK;
        if (klo + koff + BK <= khi) {
#pragma unroll
            for (int j = 0; j < 2; j++)
                ebuf[j] = *reinterpret_cast<const float4*>(a_base + aoff_e + (uint32_t)j * 64u * KDIM + koff);
#pragma unroll
            for (int j = 0; j < 4; j++)
                obuf[j] = *reinterpret_cast<const float2*>(a_base + aoff_o + (uint32_t)j * 32u * KDIM + koff);
        } else {
            // tail (final iter of final split): per-float guarded, zero-fill
            const int kmax = khi - klo;
#pragma unroll
            for (int j = 0; j < 2; j++) {
                const float* s = a_base + aoff_e + (uint32_t)j * 64u * KDIM + koff;
                int k0 = koff + ge * 4;
                ebuf[j].x = (k0 + 0 < kmax) ? s[0] : 0.f;
                ebuf[j].y = (k0 + 1 < kmax) ? s[1] : 0.f;
                ebuf[j].z = (k0 + 2 < kmax) ? s[2] : 0.f;
                ebuf[j].w = (k0 + 3 < kmax) ? s[3] : 0.f;
            }
#pragma unroll
            for (int j = 0; j < 4; j++) {
                const float* s = a_base + aoff_o + (uint32_t)j * 32u * KDIM + koff;
                int k0 = koff + go * 2;
                obuf[j].x = (k0 + 0 < kmax) ? s[0] : 0.f;
                obuf[j].y = (k0 + 1 < kmax) ? s[1] : 0.f;
            }
        }
    };

    // convert reg buffer (stage s) -> A16[s&1]
    auto convert_stage = [&](int stage) {
        char* a16 = smem + SMEM_A16(stage & 1);
#pragma unroll
        for (int j = 0; j < 2; j++) {
            uint2 p = make_uint2(pack_h2(ebuf[j].y, ebuf[j].x), pack_h2(ebuf[j].w, ebuf[j].z));
            *reinterpret_cast<uint2*>(a16 + d16_e + (uint32_t)(j * 64 * RSH * 2)) = p;
        }
#pragma unroll
        for (int j = 0; j < 4; j++)
            *reinterpret_cast<uint32_t*>(a16 + d16_o + (uint32_t)(j * 32 * RSH * 2)) =
                pack_h2(obuf[j].y, obuf[j].x);
    };

    auto load_b = [&](int stage) {
        const uint32_t b16 = sb + SMEM_B16(stage % STAGES);
        const int koff = stage * BK;
#pragma unroll
        for (int j = 0; j < 2; j++)   // B padded/zero-filled -> always safe
            cp16(b16 + d_b + (uint32_t)(j * 64 * RSH * 2),
                 b_base + boff + (uint32_t)j * 64u * KPAD + koff);
        cp_commit();
    };

    // prologue
    ldg_stage(0);
    load_b(0);
    load_b(1);
    convert_stage(0);            // waits on stage-0 LDG (one-time stall)
    ldg_stage(1);
    cp_wait1();                  // B(0) resident

    for (int i = 0; i < iters; i++) {
        __syncthreads();   // single barrier: A16[i&1] visible; WAR on reloaded B/A16 bufs
        if (i + 2 < iters) load_b(i + 2);

        // MMAs on stage i: A16[i&1] (converted last iter), B16[i%3] (waited last iter)
        const uint32_t a16 = sb + SMEM_A16(i & 1) + lm_off + (uint32_t)(wm * RSH * 2);
        const uint32_t b16 = sb + SMEM_B16(i % STAGES) + lm_off + (uint32_t)(wc * RSH * 2);
#pragma unroll
        for (int ks = 0; ks < 2; ks++) {
            uint32_t a[4][4], bf[2][4];
#pragma unroll
            for (int mi = 0; mi < 4; mi++)
                ldsm4(a[mi][0], a[mi][1], a[mi][2], a[mi][3],
                      a16 + (uint32_t)(mi * 16 * RSH * 2) + (uint32_t)(ks * 32));
#pragma unroll
            for (int nj = 0; nj < 2; nj++)
                ldsm4(bf[nj][0], bf[nj][1], bf[nj][2], bf[nj][3],
                      b16 + (uint32_t)(nj * 16 * RSH * 2) + (uint32_t)(ks * 32));
#pragma unroll
            for (int mi = 0; mi < 4; mi++) {
                mma_fp16(acc[mi][0], a[mi], bf[0][0], bf[0][2]);
                mma_fp16(acc[mi][1], a[mi], bf[0][1], bf[0][3]);
                mma_fp16(acc[mi][2], a[mi], bf[1][0], bf[1][2]);
                mma_fp16(acc[mi][3], a[mi], bf[1][1], bf[1][3]);
            }
        }

        // off critical path: convert stage i+1 (regs, LDG'd last iter), then LDG stage i+2
        if (i + 1 < iters) {
            convert_stage(i + 1);
            if (i + 2 < iters) { ldg_stage(i + 2); cp_wait1(); }
            else                cp_wait0();
        }
    }

    // write this split's partial
    float* base = g_part + (size_t)split * MDIM * NDIM;
#pragma unroll
    for (int mi = 0; mi < 4; mi++) {
        int r0 = m0 + wm + mi * 16 + lr;
#pragma unroll
        for (int ni = 0; ni < 4; ni++) {
            int c0 = wc + ni * 8 + 2 * lk;
            *reinterpret_cast<float2*>(base + (size_t)r0 * NDIM + c0) =
                make_float2(acc[mi][ni][0], acc[mi][ni][1]);
            *reinterpret_cast<float2*>(base + (size_t)(r0 + 8) * NDIM + c0) =
                make_float2(acc[mi][ni][2], acc[mi][ni][3]);
        }
    }

    // fused reduction: last CTA for this tile sums all splits in fixed order (deterministic)
    __threadfence();
    __shared__ int s_last;
    __syncthreads();
    if (tid == 0) s_last = (atomicAdd(&g_cnt[tile], 1) == SPLITS - 1) ? 1 : 0;
    __syncthreads();
    if (s_last) {
        const size_t t4 = (size_t)m0 * NDIM / 4;
#pragma unroll
        for (int j = 0; j < 16; j++) {
            size_t idx = t4 + (size_t)tid + (size_t)j * NTHREADS;
            float4 a4 = __ldcg(reinterpret_cast<const float4*>(g_part) + idx);
#pragma unroll
            for (int s = 1; s < SPLITS; s++) {
                float4 v = __ldcg(reinterpret_cast<const float4*>(g_part) +
                                  (size_t)s * (MDIM * NDIM / 4) + idx);
                a4.x += v.x; a4.y += v.y; a4.z += v.z; a4.w += v.w;
            }
            reinterpret_cast<float4*>(out)[idx] = a4;
        }
    }
}

// ---------------- launch ----------------
extern "C" void kernel_launch(void* const* d_in, const int* in_sizes, int n_in,
                              void* d_out, int out_size) {
    const float* input = (const float*)d_in[0];
    const float* w2v   = (const float*)d_in[1];
    if (n_in >= 2 && in_sizes[0] == 50000 * 128) {  // defensive: identify by size
        input = (const float*)d_in[1];
        w2v   = (const float*)d_in[0];
    }
    cudaFuncSetAttribute(gemm_fp16, cudaFuncAttributeMaxDynamicSharedMemorySize, SMEM_TOTAL);

    prep_b<<<dim3(KPAD / 32, NDIM / 32), dim3(32, 8)>>>(w2v);
    gemm_fp16<<<dim3(MDIM / BM, SPLITS), NTHREADS, SMEM_TOTAL>>>((float*)d_out, input);
}